// round 1
// baseline (speedup 1.0000x reference)
#include <cuda_runtime.h>
#include <math.h>

// Problem constants (fixed shapes from setup_inputs)
#define LL 4
#define BB 8
#define NS 1200
#define NL 128
#define CC 768
#define HH 448
#define WW 448
#define GS 56            // H/8
#define GL 16            // H/28
#define VS (GS*GS)       // 3136
#define VL (GL*GL)       // 256
#define LB (LL*BB)       // 32

// Scratch (no allocations allowed -> __device__ globals)
__device__ float g_dist_s[LB*NS];
__device__ float g_abs_s [LB*NS];
__device__ float g_dist_l[LB*NL];
__device__ float g_abs_l [LB*NL];
__device__ unsigned char g_valid_s[BB*VS];
__device__ unsigned char g_valid_l[BB*VL];
__device__ float g_loss[2*LB];
__device__ int   g_act [2*LB];

// ---------------------------------------------------------------------------
// 1) valid masks from strided samples of f_k (channel dim is 1 -> just >0)
// ---------------------------------------------------------------------------
__global__ void k_valid(const float* __restrict__ fk) {
    int t = blockIdx.x * blockDim.x + threadIdx.x;
    if (t < BB*VS) {
        int b = t / VS, p = t % VS;
        int i = p / GS, j = p % GS;
        g_valid_s[t] = fk[(size_t)b*HH*WW + (size_t)i*8*WW + j*8] > 0.f;
    } else if (t < BB*VS + BB*VL) {
        int u = t - BB*VS;
        int b = u / VL, p = u % VL;
        int i = p / GL, j = p % GL;
        g_valid_l[u] = fk[(size_t)b*HH*WW + (size_t)i*28*WW + j*28] > 0.f;
    }
}

// ---------------------------------------------------------------------------
// 2) Main HBM-bound pass: per row (l,b,n): dist = sqrt(sum_c (anchor-sel)^2)
//    and abssum = sum_c |sel|.  One warp per row, float4 loads, anchor in SMEM.
//    scale: 0 = s, 1 = l
// ---------------------------------------------------------------------------
__global__ void k_dist(const float* __restrict__ sel,
                       const float* __restrict__ ker,
                       int N, int scale) {
    __shared__ float sa[CC];
    int lb = blockIdx.y;   // l*B + b
    const float* a = ker + (size_t)lb * CC;    // kernel shape (L,B,C,1) -> contiguous C
    for (int i = threadIdx.x; i < CC; i += blockDim.x) sa[i] = a[i];
    __syncthreads();

    int warp = threadIdx.x >> 5;
    int lane = threadIdx.x & 31;
    int n = blockIdx.x * 8 + warp;
    if (n >= N) return;

    const float4* row = (const float4*)(sel + ((size_t)lb * N + n) * CC);
    const float4* av  = (const float4*)sa;

    float s2 = 0.f, sab = 0.f;
#pragma unroll
    for (int k = 0; k < CC/128; k++) {   // 6 iterations, 192 float4 per row
        float4 v  = row[k*32 + lane];
        float4 aa = av [k*32 + lane];
        float d0 = aa.x - v.x, d1 = aa.y - v.y;
        float d2 = aa.z - v.z, d3 = aa.w - v.w;
        s2  = fmaf(d0, d0, s2); s2 = fmaf(d1, d1, s2);
        s2  = fmaf(d2, d2, s2); s2 = fmaf(d3, d3, s2);
        sab += fabsf(v.x) + fabsf(v.y) + fabsf(v.z) + fabsf(v.w);
    }
#pragma unroll
    for (int o = 16; o; o >>= 1) {
        s2  += __shfl_xor_sync(0xFFFFFFFFu, s2,  o);
        sab += __shfl_xor_sync(0xFFFFFFFFu, sab, o);
    }
    if (lane == 0) {
        size_t off = (size_t)lb * N + n;
        if (scale == 0) { g_dist_s[off] = sqrtf(s2); g_abs_s[off] = sab; }
        else            { g_dist_l[off] = sqrtf(s2); g_abs_l[off] = sab; }
    }
}

// ---------------------------------------------------------------------------
// 3) Per-(scale,l,b) masked means + softplus.  64 blocks.
//    col_valid[l,n] = OR_b (abssum[l,b,n] != 0)  (abssum >= 0 always)
// ---------------------------------------------------------------------------
__global__ void k_stats(const int* __restrict__ idx_s,
                        const int* __restrict__ idx_l) {
    int gb = blockIdx.x;
    int scale = gb / LB;      // 0 = s, 1 = l
    int lb = gb % LB;
    int l = lb / BB, b = lb % BB;
    int N = scale ? NL : NS;
    int V = scale ? VL : VS;
    const float* dist = scale ? g_dist_l : g_dist_s;
    const float* ab   = scale ? g_abs_l  : g_abs_s;
    const unsigned char* valid = scale ? g_valid_l : g_valid_s;
    const int* idx = scale ? idx_l : idx_s;

    float sp = 0.f, sn = 0.f;
    int   cp = 0,   cn = 0;
    for (int n = threadIdx.x; n < N; n += blockDim.x) {
        bool colv = false;
#pragma unroll
        for (int bb = 0; bb < BB; bb++)
            colv |= (ab[((size_t)l*BB + bb)*N + n] != 0.f);
        if (!colv) continue;
        int id = idx[((size_t)l*BB + b)*N + n];
        bool mem = valid[b*V + id] != 0;
        float d = dist[(size_t)lb*N + n];
        if (mem) { sp += d; cp++; } else { sn += d; cn++; }
    }

#pragma unroll
    for (int o = 16; o; o >>= 1) {
        sp += __shfl_xor_sync(0xFFFFFFFFu, sp, o);
        sn += __shfl_xor_sync(0xFFFFFFFFu, sn, o);
        cp += __shfl_xor_sync(0xFFFFFFFFu, cp, o);
        cn += __shfl_xor_sync(0xFFFFFFFFu, cn, o);
    }
    __shared__ float rsp[8], rsn[8];
    __shared__ int   rcp[8], rcn[8];
    int warp = threadIdx.x >> 5;
    if ((threadIdx.x & 31) == 0) { rsp[warp]=sp; rsn[warp]=sn; rcp[warp]=cp; rcn[warp]=cn; }
    __syncthreads();
    if (threadIdx.x == 0) {
        float tsp = 0.f, tsn = 0.f; int tcp = 0, tcn = 0;
        for (int w = 0; w < (int)(blockDim.x >> 5); w++) {
            tsp += rsp[w]; tsn += rsn[w]; tcp += rcp[w]; tcn += rcn[w];
        }
        float ap = tsp / (float)(tcp > 1 ? tcp : 1);
        float an = tsn / (float)(tcn > 1 ? tcn : 1);
        float x = ap - an;
        // stable softplus = logaddexp(x, 0)
        float loss = (x > 0.f) ? (x + log1pf(expf(-x))) : log1pf(expf(x));
        g_loss[gb] = loss;
        g_act[gb]  = (tcp > 0 && tcn > 0) ? 1 : 0;
    }
}

// ---------------------------------------------------------------------------
// 4) Final scalar combine.
// ---------------------------------------------------------------------------
__global__ void k_final(float* __restrict__ out) {
    int t = threadIdx.x;   // 64 threads
    float v = 0.f; int c = 0;
    if (t < LB) {                          // small scale: act_s
        if (g_act[t]) { v = g_loss[t]; c = 1; }
    } else {                               // large scale: act_l & act_s
        int lb = t - LB;
        if (g_act[t] && g_act[lb]) { v = g_loss[t]; c = 1; }
    }
#pragma unroll
    for (int o = 16; o; o >>= 1) {
        v += __shfl_xor_sync(0xFFFFFFFFu, v, o);
        c += __shfl_xor_sync(0xFFFFFFFFu, c, o);
    }
    __shared__ float sv[2]; __shared__ int sc[2];
    int warp = t >> 5;
    if ((t & 31) == 0) { sv[warp] = v; sc[warp] = c; }
    __syncthreads();
    if (t == 0) {
        float total = sv[0] + sv[1];
        int times = sc[0] + sc[1];
        out[0] = (times > 0) ? total / (float)times : 0.f;
    }
}

// ---------------------------------------------------------------------------
extern "C" void kernel_launch(void* const* d_in, const int* in_sizes, int n_in,
                              void* d_out, int out_size) {
    const float* sel_s = (const float*)d_in[0];
    const int*   idx_s = (const int*)  d_in[1];
    const float* sel_l = (const float*)d_in[2];
    const int*   idx_l = (const int*)  d_in[3];
    const float* ker_s = (const float*)d_in[4];
    const float* ker_l = (const float*)d_in[5];
    const float* fk    = (const float*)d_in[6];

    k_valid<<<(BB*VS + BB*VL + 255)/256, 256>>>(fk);

    dim3 gs((NS + 7)/8, LB);
    k_dist<<<gs, 256>>>(sel_s, ker_s, NS, 0);
    dim3 gl((NL + 7)/8, LB);
    k_dist<<<gl, 256>>>(sel_l, ker_l, NL, 1);

    k_stats<<<2*LB, 256>>>(idx_s, idx_l);
    k_final<<<1, 64>>>((float*)d_out);
}

// round 3
// speedup vs baseline: 1.1603x; 1.1603x over previous
#include <cuda_runtime.h>
#include <math.h>

// Problem constants (fixed shapes from setup_inputs)
#define LL 4
#define BB 8
#define NS 1200
#define NL 128
#define CC 768
#define HH 448
#define WW 448
#define GS 56            // H/8
#define GL 16            // H/28
#define VS (GS*GS)       // 3136
#define VL (GL*GL)       // 256
#define LB (LL*BB)       // 32
#define CWS ((NS+31)/32) // 38 colv words per l (small)
#define CWL ((NL+31)/32) // 4  colv words per l (large)

// Scratch (no allocations allowed -> __device__ globals).
// NOTE: these must be referenced from DEVICE code only (host-side symbol
// address is the shadow, not the device pointer — R2 bug).
__device__ float g_dist_s[LB*NS];
__device__ float g_dist_l[LB*NL];
__device__ unsigned g_colv_s[LL*CWS];
__device__ unsigned g_colv_l[LL*CWL];
__device__ unsigned char g_valid_s[BB*VS];
__device__ unsigned char g_valid_l[BB*VL];
__device__ float g_loss[2*LB];
__device__ int   g_act [2*LB];

// ---------------------------------------------------------------------------
// 1) valid masks from strided samples of f_k; also zero the colv bitmasks.
// ---------------------------------------------------------------------------
__global__ void k_valid(const float* __restrict__ fk) {
    int t = blockIdx.x * blockDim.x + threadIdx.x;
    if (t < LL*CWS) g_colv_s[t] = 0u;
    if (t < LL*CWL) g_colv_l[t] = 0u;
    if (t < BB*VS) {
        int b = t / VS, p = t % VS;
        int i = p / GS, j = p % GS;
        g_valid_s[t] = fk[(size_t)b*HH*WW + (size_t)i*8*WW + j*8] > 0.f;
    } else if (t < BB*VS + BB*VL) {
        int u = t - BB*VS;
        int b = u / VL, p = u % VL;
        int i = p / GL, j = p % GL;
        g_valid_l[u] = fk[(size_t)b*HH*WW + (size_t)i*28*WW + j*28] > 0.f;
    }
}

// ---------------------------------------------------------------------------
// 2) Main HBM-bound pass: per row (l,b,n): dist = sqrt(sum_c (anchor-sel)^2)
//    and abssum = sum_c |sel| -> sets colv bit if nonzero.
//    One warp per row, float4 loads, anchor staged in SMEM.
//    scale: 0 = s, 1 = l  (selects device-global scratch inside device code)
// ---------------------------------------------------------------------------
__global__ void k_dist(const float* __restrict__ sel,
                       const float* __restrict__ ker,
                       int N, int scale) {
    __shared__ float sa[CC];
    int lb = blockIdx.y;   // l*B + b
    int l  = lb / BB;
    const float* a = ker + (size_t)lb * CC;   // kernel shape (L,B,C,1) -> contiguous C
    for (int i = threadIdx.x; i < CC; i += blockDim.x) sa[i] = a[i];
    __syncthreads();

    int warp = threadIdx.x >> 5;
    int lane = threadIdx.x & 31;
    int n = blockIdx.x * 8 + warp;
    if (n >= N) return;

    const float4* row = (const float4*)(sel + ((size_t)lb * N + n) * CC);
    const float4* av  = (const float4*)sa;

    float s2 = 0.f, sab = 0.f;
#pragma unroll
    for (int k = 0; k < CC/128; k++) {   // 6 iterations, 192 float4 per row
        float4 v  = row[k*32 + lane];
        float4 aa = av [k*32 + lane];
        float d0 = aa.x - v.x, d1 = aa.y - v.y;
        float d2 = aa.z - v.z, d3 = aa.w - v.w;
        s2  = fmaf(d0, d0, s2); s2 = fmaf(d1, d1, s2);
        s2  = fmaf(d2, d2, s2); s2 = fmaf(d3, d3, s2);
        sab += fabsf(v.x) + fabsf(v.y) + fabsf(v.z) + fabsf(v.w);
    }
#pragma unroll
    for (int o = 16; o; o >>= 1) {
        s2  += __shfl_xor_sync(0xFFFFFFFFu, s2,  o);
        sab += __shfl_xor_sync(0xFFFFFFFFu, sab, o);
    }
    if (lane == 0) {
        size_t off = (size_t)lb * N + n;
        if (scale == 0) {
            g_dist_s[off] = sqrtf(s2);
            if (sab != 0.f) atomicOr(&g_colv_s[l*CWS + (n >> 5)], 1u << (n & 31));
        } else {
            g_dist_l[off] = sqrtf(s2);
            if (sab != 0.f) atomicOr(&g_colv_l[l*CWL + (n >> 5)], 1u << (n & 31));
        }
    }
}

// ---------------------------------------------------------------------------
// 3) Per-(scale,l,b) masked means + softplus.  64 blocks.
// ---------------------------------------------------------------------------
__global__ void k_stats(const int* __restrict__ idx_s,
                        const int* __restrict__ idx_l) {
    int gb = blockIdx.x;
    int scale = gb / LB;      // 0 = s, 1 = l
    int lb = gb % LB;
    int l = lb / BB, b = lb % BB;
    int N = scale ? NL : NS;
    int V = scale ? VL : VS;
    const float* dist = scale ? g_dist_l : g_dist_s;
    const unsigned* colv = scale ? (g_colv_l + l*CWL) : (g_colv_s + l*CWS);
    const unsigned char* valid = scale ? g_valid_l : g_valid_s;
    const int* idx = scale ? idx_l : idx_s;

    float sp = 0.f, sn = 0.f;
    int   cp = 0,   cn = 0;
    for (int n = threadIdx.x; n < N; n += blockDim.x) {
        if (!((colv[n >> 5] >> (n & 31)) & 1u)) continue;
        int id = idx[((size_t)l*BB + b)*N + n];
        float d = dist[(size_t)lb*N + n];
        bool mem = valid[b*V + id] != 0;
        if (mem) { sp += d; cp++; } else { sn += d; cn++; }
    }

#pragma unroll
    for (int o = 16; o; o >>= 1) {
        sp += __shfl_xor_sync(0xFFFFFFFFu, sp, o);
        sn += __shfl_xor_sync(0xFFFFFFFFu, sn, o);
        cp += __shfl_xor_sync(0xFFFFFFFFu, cp, o);
        cn += __shfl_xor_sync(0xFFFFFFFFu, cn, o);
    }
    __shared__ float rsp[8], rsn[8];
    __shared__ int   rcp[8], rcn[8];
    int warp = threadIdx.x >> 5;
    if ((threadIdx.x & 31) == 0) { rsp[warp]=sp; rsn[warp]=sn; rcp[warp]=cp; rcn[warp]=cn; }
    __syncthreads();
    if (threadIdx.x == 0) {
        float tsp = 0.f, tsn = 0.f; int tcp = 0, tcn = 0;
        for (int w = 0; w < (int)(blockDim.x >> 5); w++) {
            tsp += rsp[w]; tsn += rsn[w]; tcp += rcp[w]; tcn += rcn[w];
        }
        float ap = tsp / (float)(tcp > 1 ? tcp : 1);
        float an = tsn / (float)(tcn > 1 ? tcn : 1);
        float x = ap - an;
        // stable softplus = logaddexp(x, 0)
        float loss = (x > 0.f) ? (x + log1pf(expf(-x))) : log1pf(expf(x));
        g_loss[gb] = loss;
        g_act[gb]  = (tcp > 0 && tcn > 0) ? 1 : 0;
    }
}

// ---------------------------------------------------------------------------
// 4) Final scalar combine.
// ---------------------------------------------------------------------------
__global__ void k_final(float* __restrict__ out) {
    int t = threadIdx.x;   // 64 threads
    float v = 0.f; int c = 0;
    if (t < LB) {                          // small scale: act_s
        if (g_act[t]) { v = g_loss[t]; c = 1; }
    } else {                               // large scale: act_l & act_s
        int lb = t - LB;
        if (g_act[t] && g_act[lb]) { v = g_loss[t]; c = 1; }
    }
#pragma unroll
    for (int o = 16; o; o >>= 1) {
        v += __shfl_xor_sync(0xFFFFFFFFu, v, o);
        c += __shfl_xor_sync(0xFFFFFFFFu, c, o);
    }
    __shared__ float sv[2]; __shared__ int sc[2];
    int warp = t >> 5;
    if ((t & 31) == 0) { sv[warp] = v; sc[warp] = c; }
    __syncthreads();
    if (t == 0) {
        float total = sv[0] + sv[1];
        int times = sc[0] + sc[1];
        out[0] = (times > 0) ? total / (float)times : 0.f;
    }
}

// ---------------------------------------------------------------------------
extern "C" void kernel_launch(void* const* d_in, const int* in_sizes, int n_in,
                              void* d_out, int out_size) {
    const float* sel_s = (const float*)d_in[0];
    const int*   idx_s = (const int*)  d_in[1];
    const float* sel_l = (const float*)d_in[2];
    const int*   idx_l = (const int*)  d_in[3];
    const float* ker_s = (const float*)d_in[4];
    const float* ker_l = (const float*)d_in[5];
    const float* fk    = (const float*)d_in[6];

    k_valid<<<(BB*VS + BB*VL + 255)/256, 256>>>(fk);

    dim3 gs((NS + 7)/8, LB);
    k_dist<<<gs, 256>>>(sel_s, ker_s, NS, 0);
    dim3 gl((NL + 7)/8, LB);
    k_dist<<<gl, 256>>>(sel_l, ker_l, NL, 1);

    k_stats<<<2*LB, 256>>>(idx_s, idx_l);
    k_final<<<1, 64>>>((float*)d_out);
}

// round 4
// speedup vs baseline: 1.4468x; 1.2470x over previous
#include <cuda_runtime.h>
#include <math.h>

// Problem constants (fixed shapes from setup_inputs)
#define LL 4
#define BB 8
#define NS 1200
#define NL 128
#define CC 768
#define HH 448
#define WW 448
#define GS 56            // H/8
#define GL 16            // H/28
#define VS (GS*GS)       // 3136
#define VL (GL*GL)       // 256
#define LB (LL*BB)       // 32
#define CWS ((NS+31)/32) // 38 colv words per l (small)
#define CWL ((NL+31)/32) // 4  colv words per l (large)
#define NBS 150          // blocks per lb for small scale in k_dist (1200/8)
#define NBL 16           // blocks per lb for large scale in k_dist (128/8)

// Scratch (no allocations allowed -> __device__ globals).
// Referenced from DEVICE code only.
__device__ float g_dist_s[LB*NS];
__device__ float g_dist_l[LB*NL];
__device__ unsigned g_colv_s[LL*CWS];
__device__ unsigned g_colv_l[LL*CWL];
__device__ unsigned char g_valid_s[BB*VS];
__device__ unsigned char g_valid_l[BB*VL];
__device__ float g_sp[2*LB];
__device__ float g_sn[2*LB];
__device__ int   g_cp[2*LB];
__device__ int   g_cn[2*LB];

// ---------------------------------------------------------------------------
// 1) valid masks from strided samples of f_k; zero colv bitmasks + accumulators.
// ---------------------------------------------------------------------------
__global__ void k_valid(const float* __restrict__ fk) {
    int t = blockIdx.x * blockDim.x + threadIdx.x;
    if (t < LL*CWS) g_colv_s[t] = 0u;
    if (t < LL*CWL) g_colv_l[t] = 0u;
    if (t < 2*LB) { g_sp[t] = 0.f; g_sn[t] = 0.f; g_cp[t] = 0; g_cn[t] = 0; }
    if (t < BB*VS) {
        int b = t / VS, p = t % VS;
        int i = p / GS, j = p % GS;
        g_valid_s[t] = fk[(size_t)b*HH*WW + (size_t)i*8*WW + j*8] > 0.f;
    } else if (t < BB*VS + BB*VL) {
        int u = t - BB*VS;
        int b = u / VL, p = u % VL;
        int i = p / GL, j = p % GL;
        g_valid_l[u] = fk[(size_t)b*HH*WW + (size_t)i*28*WW + j*28] > 0.f;
    }
}

// ---------------------------------------------------------------------------
// 2) Main HBM-bound pass (both scales in one launch):
//    per row (l,b,n): dist = sqrt(sum_c (anchor-sel)^2) and
//    abssum = sum_c |sel| -> sets colv bit if nonzero.
//    One warp per row, float4 loads, anchor staged in SMEM.
//    blockIdx.x < NBS -> small scale; else large scale.
// ---------------------------------------------------------------------------
__global__ void k_dist(const float* __restrict__ sel_s,
                       const float* __restrict__ ker_s,
                       const float* __restrict__ sel_l,
                       const float* __restrict__ ker_l) {
    __shared__ float sa[CC];
    int lb = blockIdx.y;   // l*B + b
    int l  = lb / BB;
    int scale = (blockIdx.x >= NBS) ? 1 : 0;
    int bx = scale ? (blockIdx.x - NBS) : blockIdx.x;
    int N = scale ? NL : NS;
    const float* sel = scale ? sel_l : sel_s;
    const float* ker = scale ? ker_l : ker_s;

    const float* a = ker + (size_t)lb * CC;   // kernel shape (L,B,C,1) -> contiguous C
    for (int i = threadIdx.x; i < CC; i += blockDim.x) sa[i] = a[i];
    __syncthreads();

    int warp = threadIdx.x >> 5;
    int lane = threadIdx.x & 31;
    int n = bx * 8 + warp;
    if (n >= N) return;

    const float4* row = (const float4*)(sel + ((size_t)lb * N + n) * CC);
    const float4* av  = (const float4*)sa;

    float s2 = 0.f, sab = 0.f;
#pragma unroll
    for (int k = 0; k < CC/128; k++) {   // 6 iterations, 192 float4 per row
        float4 v  = row[k*32 + lane];
        float4 aa = av [k*32 + lane];
        float d0 = aa.x - v.x, d1 = aa.y - v.y;
        float d2 = aa.z - v.z, d3 = aa.w - v.w;
        s2  = fmaf(d0, d0, s2); s2 = fmaf(d1, d1, s2);
        s2  = fmaf(d2, d2, s2); s2 = fmaf(d3, d3, s2);
        sab += fabsf(v.x) + fabsf(v.y) + fabsf(v.z) + fabsf(v.w);
    }
#pragma unroll
    for (int o = 16; o; o >>= 1) {
        s2  += __shfl_xor_sync(0xFFFFFFFFu, s2,  o);
        sab += __shfl_xor_sync(0xFFFFFFFFu, sab, o);
    }
    if (lane == 0) {
        size_t off = (size_t)lb * N + n;
        if (scale == 0) {
            g_dist_s[off] = sqrtf(s2);
            if (sab != 0.f) atomicOr(&g_colv_s[l*CWS + (n >> 5)], 1u << (n & 31));
        } else {
            g_dist_l[off] = sqrtf(s2);
            if (sab != 0.f) atomicOr(&g_colv_l[l*CWL + (n >> 5)], 1u << (n & 31));
        }
    }
}

// ---------------------------------------------------------------------------
// 3) Masked accumulation: one element per thread, atomic partials.
//    grid = (5, 64): blockIdx.y = gb (scale*LB + lb), blockIdx.x = chunk.
// ---------------------------------------------------------------------------
__global__ void k_stats(const int* __restrict__ idx_s,
                        const int* __restrict__ idx_l) {
    int gb = blockIdx.y;
    int scale = gb / LB;      // 0 = s, 1 = l
    int lb = gb % LB;
    int l = lb / BB, b = lb % BB;
    int N = scale ? NL : NS;
    int V = scale ? VL : VS;
    const float* dist = scale ? g_dist_l : g_dist_s;
    const unsigned* colv = scale ? (g_colv_l + l*CWL) : (g_colv_s + l*CWS);
    const unsigned char* valid = scale ? g_valid_l : g_valid_s;
    const int* idx = scale ? idx_l : idx_s;

    int n = blockIdx.x * blockDim.x + threadIdx.x;
    float sp = 0.f, sn = 0.f;
    int   cp = 0,   cn = 0;
    if (n < N && ((colv[n >> 5] >> (n & 31)) & 1u)) {
        int id = idx[((size_t)l*BB + b)*N + n];
        float d = dist[(size_t)lb*N + n];
        bool mem = valid[b*V + id] != 0;
        if (mem) { sp = d; cp = 1; } else { sn = d; cn = 1; }
    }

#pragma unroll
    for (int o = 16; o; o >>= 1) {
        sp += __shfl_xor_sync(0xFFFFFFFFu, sp, o);
        sn += __shfl_xor_sync(0xFFFFFFFFu, sn, o);
        cp += __shfl_xor_sync(0xFFFFFFFFu, cp, o);
        cn += __shfl_xor_sync(0xFFFFFFFFu, cn, o);
    }
    if ((threadIdx.x & 31) == 0) {
        if (sp != 0.f) atomicAdd(&g_sp[gb], sp);
        if (sn != 0.f) atomicAdd(&g_sn[gb], sn);
        if (cp)        atomicAdd(&g_cp[gb], cp);
        if (cn)        atomicAdd(&g_cn[gb], cn);
    }
}

// ---------------------------------------------------------------------------
// 4) Final: per-gb softplus/act, then scalar combine. One block, 64 threads.
// ---------------------------------------------------------------------------
__global__ void k_final(float* __restrict__ out) {
    __shared__ float s_loss[2*LB];
    __shared__ int   s_act [2*LB];
    int t = threadIdx.x;   // 64 threads
    {
        int tcp = g_cp[t], tcn = g_cn[t];
        float ap = g_sp[t] / (float)(tcp > 1 ? tcp : 1);
        float an = g_sn[t] / (float)(tcn > 1 ? tcn : 1);
        float x = ap - an;
        float loss = (x > 0.f) ? (x + log1pf(expf(-x))) : log1pf(expf(x));
        s_loss[t] = loss;
        s_act[t]  = (tcp > 0 && tcn > 0) ? 1 : 0;
    }
    __syncthreads();

    float v = 0.f; int c = 0;
    if (t < LB) {                          // small scale: act_s
        if (s_act[t]) { v = s_loss[t]; c = 1; }
    } else {                               // large scale: act_l & act_s
        if (s_act[t] && s_act[t - LB]) { v = s_loss[t]; c = 1; }
    }
#pragma unroll
    for (int o = 16; o; o >>= 1) {
        v += __shfl_xor_sync(0xFFFFFFFFu, v, o);
        c += __shfl_xor_sync(0xFFFFFFFFu, c, o);
    }
    __shared__ float sv[2]; __shared__ int sc[2];
    int warp = t >> 5;
    if ((t & 31) == 0) { sv[warp] = v; sc[warp] = c; }
    __syncthreads();
    if (t == 0) {
        float total = sv[0] + sv[1];
        int times = sc[0] + sc[1];
        out[0] = (times > 0) ? total / (float)times : 0.f;
    }
}

// ---------------------------------------------------------------------------
extern "C" void kernel_launch(void* const* d_in, const int* in_sizes, int n_in,
                              void* d_out, int out_size) {
    const float* sel_s = (const float*)d_in[0];
    const int*   idx_s = (const int*)  d_in[1];
    const float* sel_l = (const float*)d_in[2];
    const int*   idx_l = (const int*)  d_in[3];
    const float* ker_s = (const float*)d_in[4];
    const float* ker_l = (const float*)d_in[5];
    const float* fk    = (const float*)d_in[6];

    k_valid<<<(BB*VS + BB*VL + 255)/256, 256>>>(fk);

    dim3 gd(NBS + NBL, LB);
    k_dist<<<gd, 256>>>(sel_s, ker_s, sel_l, ker_l);

    dim3 gst((NS + 255)/256, 2*LB);   // (5, 64)
    k_stats<<<gst, 256>>>(idx_s, idx_l);

    k_final<<<1, 64>>>((float*)d_out);
}